// round 1
// baseline (speedup 1.0000x reference)
#include <cuda_runtime.h>

// SSIM over 128 independent 384x384 fp32 image pairs, 7x7 VALID box filter,
// skimage-style sample-covariance correction, global mean -> scalar.
//
// Design: vertical-first separable box sums. Each CTA owns (image, row-band).
// Thread t owns input columns t and t+256; maintains 5 running column sums
// over a sliding 7-row window (raw rows kept in a shared ring, thread-private
// access -> no sync needed for the ring). Per output row, column sums are
// published to shared V[5][384]; threads then compute horizontal 7-sums for
// PAIRS of adjacent outputs via float2 LDS (conflict-free, ~halves shared
// bytes vs naive), apply the SSIM formula, and accumulate locally.
// Deterministic block reduce -> __device__ partials -> tiny final reduce.

#define WINR   7
#define IMG_H  384
#define IMG_W  384
#define OUT_W  378          // IMG_W - 6
#define OUT_H  378
#define NIMG   128          // 32 * 4
#define BANDS  4
#define BAND_ROWS 96        // ceil-ish; last band clipped to OUT_H
#define NTHREADS 256

__device__ float g_partials[NIMG * BANDS];

__global__ __launch_bounds__(NTHREADS, 4)
void ssim_band_kernel(const float* __restrict__ pred,
                      const float* __restrict__ actual) {
    const int img  = blockIdx.y;
    const int band = blockIdx.x;
    const int ob = band * BAND_ROWS;
    const int oe = min(ob + BAND_ROWS, OUT_H);

    __shared__ __align__(16) float ringX[WINR][IMG_W];
    __shared__ __align__(16) float ringY[WINR][IMG_W];
    __shared__ __align__(16) float Vs[5][IMG_W];
    __shared__ float red[NTHREADS];

    const float* __restrict__ xim = pred   + (size_t)img * IMG_H * IMG_W;
    const float* __restrict__ yim = actual + (size_t)img * IMG_H * IMG_W;

    const int t  = threadIdx.x;
    const int c0 = t;
    const int c1 = t + NTHREADS;            // second column, valid if t < 128
    const bool has2 = (c1 < IMG_W);

    // running vertical sums for the two owned columns
    float sx0=0.f, sy0=0.f, sxx0=0.f, syy0=0.f, sxy0=0.f;
    float sx1=0.f, sy1=0.f, sxx1=0.f, syy1=0.f, sxy1=0.f;

    // ---- prologue: rows ob .. ob+5 ----
    #pragma unroll 1
    for (int r = ob; r < ob + 6; ++r) {
        const int s = r % WINR;
        float x = xim[r * IMG_W + c0];
        float y = yim[r * IMG_W + c0];
        ringX[s][c0] = x; ringY[s][c0] = y;
        sx0 += x; sy0 += y; sxx0 += x*x; syy0 += y*y; sxy0 += x*y;
        if (has2) {
            float x2 = xim[r * IMG_W + c1];
            float y2 = yim[r * IMG_W + c1];
            ringX[s][c1] = x2; ringY[s][c1] = y2;
            sx1 += x2; sy1 += y2; sxx1 += x2*x2; syy1 += y2*y2; sxy1 += x2*y2;
        }
    }

    const float inv_np = 1.0f / 49.0f;
    const float covn   = 49.0f / 48.0f;
    const float C1v    = 0.01f * 0.01f;     // (K1*L)^2
    const float C2v    = 0.03f * 0.03f;     // (K2*L)^2

    float acc = 0.0f;

    #pragma unroll 1
    for (int orow = ob; orow < oe; ++orow) {
        // subtract row (orow-1) leaving the window
        if (orow > ob) {
            const int s = (orow - 1) % WINR;
            float x = ringX[s][c0], y = ringY[s][c0];
            sx0 -= x; sy0 -= y; sxx0 -= x*x; syy0 -= y*y; sxy0 -= x*y;
            if (has2) {
                float x2 = ringX[s][c1], y2 = ringY[s][c1];
                sx1 -= x2; sy1 -= y2; sxx1 -= x2*x2; syy1 -= y2*y2; sxy1 -= x2*y2;
            }
        }
        // add row (orow+6); slot (orow+6)%7 == (orow-1)%7, safe after subtract
        {
            const int r = orow + 6;
            const int s = r % WINR;
            float x = xim[r * IMG_W + c0];
            float y = yim[r * IMG_W + c0];
            ringX[s][c0] = x; ringY[s][c0] = y;
            sx0 += x; sy0 += y; sxx0 += x*x; syy0 += y*y; sxy0 += x*y;
            if (has2) {
                float x2 = xim[r * IMG_W + c1];
                float y2 = yim[r * IMG_W + c1];
                ringX[s][c1] = x2; ringY[s][c1] = y2;
                sx1 += x2; sy1 += y2; sxx1 += x2*x2; syy1 += y2*y2; sxy1 += x2*y2;
            }
        }

        // publish column sums
        Vs[0][c0]=sx0; Vs[1][c0]=sy0; Vs[2][c0]=sxx0; Vs[3][c0]=syy0; Vs[4][c0]=sxy0;
        if (has2) {
            Vs[0][c1]=sx1; Vs[1][c1]=sy1; Vs[2][c1]=sxx1; Vs[3][c1]=syy1; Vs[4][c1]=sxy1;
        }
        __syncthreads();

        // horizontal 7-sums: thread t handles output pair (2t, 2t+1); OUT_W=378=2*189
        if (t < OUT_W / 2) {
            const int o = 2 * t;
            float w0[5], w1[5];
            #pragma unroll
            for (int q = 0; q < 5; ++q) {
                const float2* vq = reinterpret_cast<const float2*>(&Vs[q][o]);
                float2 p0 = vq[0];
                float2 p1 = vq[1];
                float2 p2 = vq[2];
                float2 p3 = vq[3];
                float s6 = p0.y + p1.x + p1.y + p2.x + p2.y + p3.x; // v1..v6
                w0[q] = s6 + p0.x;
                w1[q] = s6 + p3.y;
            }
            #pragma unroll
            for (int which = 0; which < 2; ++which) {
                const float* w = which ? w1 : w0;
                float ux  = w[0] * inv_np;
                float uy  = w[1] * inv_np;
                float uxx = w[2] * inv_np;
                float uyy = w[3] * inv_np;
                float uxy = w[4] * inv_np;
                float vx  = covn * (uxx - ux * ux);
                float vy  = covn * (uyy - uy * uy);
                float vxy = covn * (uxy - ux * uy);
                float num = (2.0f * ux * uy + C1v) * (2.0f * vxy + C2v);
                float den = (ux * ux + uy * uy + C1v) * (vx + vy + C2v);
                acc += __fdividef(num, den);
            }
        }
        __syncthreads();   // protect Vs before next row overwrites it
    }

    // deterministic block reduction
    red[t] = acc;
    __syncthreads();
    #pragma unroll
    for (int s = NTHREADS / 2; s > 0; s >>= 1) {
        if (t < s) red[t] += red[t + s];
        __syncthreads();
    }
    if (t == 0) g_partials[img * BANDS + band] = red[0];
}

__global__ void ssim_reduce_kernel(float* __restrict__ out) {
    __shared__ float red[NIMG * BANDS];
    const int t = threadIdx.x;
    red[t] = g_partials[t];
    __syncthreads();
    #pragma unroll
    for (int s = (NIMG * BANDS) / 2; s > 0; s >>= 1) {
        if (t < s) red[t] += red[t + s];
        __syncthreads();
    }
    if (t == 0) {
        out[0] = red[0] * (1.0f / ((float)NIMG * (float)OUT_W * (float)OUT_H));
    }
}

extern "C" void kernel_launch(void* const* d_in, const int* in_sizes, int n_in,
                              void* d_out, int out_size) {
    const float* pred   = (const float*)d_in[0];
    const float* actual = (const float*)d_in[1];
    float* out = (float*)d_out;

    dim3 grid(BANDS, NIMG);
    ssim_band_kernel<<<grid, NTHREADS>>>(pred, actual);
    ssim_reduce_kernel<<<1, NIMG * BANDS>>>(out);
}